// round 13
// baseline (speedup 1.0000x reference)
#include <cuda_runtime.h>
#include <math.h>

// Shapes
//   amplitudes, frequencies : [8, 250, 100] f32
//   out = concat( amp_env [8, 64000, 100], freq_env [8, 250, 100] )  f32
#define B            8
#define FRAMES       250
#define CH           100
#define CTRL_ELEMS   (B * FRAMES * CH)        // 200000
#define T_OUT        64000
#define HOP          256                      // 64000 / 250
#define ENV_ELEMS    (B * T_OUT * CH)         // 51200000
#define SEGS         (B * FRAMES)             // 2000 segments
#define SEG_VEC4     (HOP * (CH / 4))         // 6400 float4 per segment
#define UP_THREADS   400                      // 16 rows x 25 float4-groups
#define STORES       16                       // float4 stores per thread

// Scratch for scaled+nyquist-masked amplitudes (no cudaMalloc allowed).
__device__ __align__(16) float g_amps[CTRL_ELEMS];

// ---------------------------------------------------------------------------
// Kernel 1: get_controls — amp scaling, freq sigmoid mapping, nyquist mask.
// Writes freqs directly into the tail of d_out, masked amps into g_amps.
// Triggers programmatic launch completion so the dependent upsample kernel's
// prologue overlaps with this kernel's tail.
// ---------------------------------------------------------------------------
__global__ void controls_kernel(const float* __restrict__ amp_in,
                                const float* __restrict__ freq_in,
                                float* __restrict__ freq_out) {
    int idx = blockIdx.x * blockDim.x + threadIdx.x;
    if (idx < CTRL_ELEMS) {
        const float LOG10_F  = 2.302585092994046f;   // ln(10)
        const float MIDI_MAX = 119.21309485364912f;  // 12*(log2 8000-log2 440)+69
        const float NYQ      = 22050.0f;             // SR / 2

        // frequencies_sigmoid
        float f  = freq_in[idx];
        float uf = 1.0f / (1.0f + expf(-f));
        float freq = 440.0f * exp2f((uf * MIDI_MAX - 69.0f) * (1.0f / 12.0f));

        // scale_function: 2 * sigmoid(a)^ln(10) + 1e-7
        float a  = amp_in[idx];
        float sa = 1.0f / (1.0f + expf(-a));
        float amp = 2.0f * powf(sa, LOG10_F) + 1e-7f;

        // remove_above_nyquist: harmonic index = (idx % 100) + 1
        int k = idx - (idx / CH) * CH;            // channel index 0..99
        float h = (float)(k + 1);
        float aa = ((freq * h < NYQ) ? 1.0f : 0.0f) + 1e-4f;

        g_amps[idx]   = amp * aa;
        freq_out[idx] = freq;
    }
#if __CUDA_ARCH__ >= 900
    cudaTriggerProgrammaticLaunchCompletion();
#endif
}

// ---------------------------------------------------------------------------
// Kernel 2: register-resident 2-tap hann crossfade, 16 stores per thread
// (measured-optimal point of the stores-per-endpoint-load ladder).
//
// One block per segment (b, j). Thread tid owns fixed channel float4-group
// c4 = tid % 25 and base row r0 = tid / 25 (0..15); endpoints x0/x1 loaded
// ONCE from g_amps, d = x1 - x0, then 16 fully coalesced float4 stores:
//   iteration k writes float4 index seg*6400 + 400k + tid (row 16k + r0),
//   weight w = sw[r0 + 16k]:  out = x0 + d * w,  w[r] = 0.5 - 0.5*cospi(r/256)
//
// PDL: the window table, index math and barrier all run BEFORE
// cudaGridDependencySynchronize(), overlapping with controls_kernel; only
// the g_amps loads wait on it.
// ---------------------------------------------------------------------------
__global__ __launch_bounds__(UP_THREADS) void upsample_kernel(
        float4* __restrict__ out) {
    __shared__ float sw[HOP];

    const int tid = threadIdx.x;
    const int seg = blockIdx.x;

    if (tid < HOP) {
        sw[tid] = 0.5f - 0.5f * cospif((float)tid * (1.0f / 256.0f));
    }

    int segn = seg + 1;
    if (segn % FRAMES == 0) segn = seg;       // clamp: frame 250 == frame 249

    const int c4 = tid % 25;                  // channel float4-group (fixed)
    const int r0 = tid / 25;                  // base row (0..15)

    __syncthreads();

#if __CUDA_ARCH__ >= 900
    cudaGridDependencySynchronize();          // wait for g_amps to be valid
#endif

    const float4 x0 = *reinterpret_cast<const float4*>(&g_amps[seg  * CH + c4 * 4]);
    const float4 x1 = *reinterpret_cast<const float4*>(&g_amps[segn * CH + c4 * 4]);
    float4 d;
    d.x = x1.x - x0.x;
    d.y = x1.y - x0.y;
    d.z = x1.z - x0.z;
    d.w = x1.w - x0.w;

    float4* o = out + (size_t)seg * SEG_VEC4 + tid;

#pragma unroll
    for (int k = 0; k < STORES; k++) {
        const float w = sw[r0 + 16 * k];
        float4 v;
        v.x = fmaf(d.x, w, x0.x);
        v.y = fmaf(d.y, w, x0.y);
        v.z = fmaf(d.z, w, x0.z);
        v.w = fmaf(d.w, w, x0.w);
        o[UP_THREADS * k] = v;
    }
}

// ---------------------------------------------------------------------------
extern "C" void kernel_launch(void* const* d_in, const int* in_sizes, int n_in,
                              void* d_out, int out_size) {
    const float* amps  = (const float*)d_in[0];
    const float* freqs = (const float*)d_in[1];
    float* out = (float*)d_out;

    controls_kernel<<<(CTRL_ELEMS + 255) / 256, 256>>>(amps, freqs,
                                                       out + ENV_ELEMS);

    // Upsample launched with programmatic stream serialization: it may begin
    // (window table + index prologue) while controls_kernel drains; the
    // device-side cudaGridDependencySynchronize() guards the g_amps reads.
    cudaLaunchConfig_t cfg = {};
    cfg.gridDim  = dim3(SEGS, 1, 1);
    cfg.blockDim = dim3(UP_THREADS, 1, 1);
    cfg.dynamicSmemBytes = 0;
    cfg.stream = 0;
    cudaLaunchAttribute attr[1];
    attr[0].id = cudaLaunchAttributeProgrammaticStreamSerialization;
    attr[0].val.programmaticStreamSerializationAllowed = 1;
    cfg.attrs = attr;
    cfg.numAttrs = 1;
    cudaLaunchKernelEx(&cfg, upsample_kernel, (float4*)out);
}

// round 14
// speedup vs baseline: 1.3973x; 1.3973x over previous
#include <cuda_runtime.h>
#include <math.h>

// Shapes
//   amplitudes, frequencies : [8, 250, 100] f32
//   out = concat( amp_env [8, 64000, 100], freq_env [8, 250, 100] )  f32
#define B            8
#define FRAMES       250
#define CH           100
#define CTRL_ELEMS   (B * FRAMES * CH)        // 200000
#define T_OUT        64000
#define HOP          256                      // 64000 / 250
#define ENV_ELEMS    (B * T_OUT * CH)         // 51200000
#define SEGS         (B * FRAMES)             // 2000 segments
#define SEG_VEC4     (HOP * (CH / 4))         // 6400 float4 per segment
#define UP_THREADS   400                      // 16 rows x 25 float4-groups
#define STORES       16                       // float4 stores per thread

// ---------------------------------------------------------------------------
// Single fused kernel: one block per segment (b, j), 400 threads.
//
// Prologue (overlapped):
//   - threads 0..199 issue the 2 controls LDGs for (seg, ch) / (segn, ch)
//     FIRST, then finish the sigmoid/exp/pow math once data arrives:
//       amp  = (2*sigmoid(a)^ln(10) + 1e-7) * ((freq*harm < SR/2) + 1e-4)
//       freq = 440 * 2^((sigmoid(f)*MIDI_MAX - 69)/12)
//     x0 -> s_x0, x1 -> s_x1; the which=0 half also writes this segment's
//     100 frequency outputs (each segment covered exactly once by its block).
//   - threads 200..399 build the 256-entry hann half-window while those
//     LDGs are in flight.
//   One barrier.
//
// Store phase (the measured-optimal R10 engine, bit-identical):
//   thread tid owns fixed channel float4-group c4 = tid % 25 and base row
//   r0 = tid / 25 (0..15); endpoints read once from smem, d = x1 - x0, then
//   16 fully coalesced float4 stores, iteration k at float4 index
//   seg*6400 + 400k + tid (row 16k + r0), weight w = sw[r0 + 16k]:
//       out = x0 + d * w,   w[r] = 0.5 - 0.5*cospi(r/256)
//
// ~4-5 blocks co-resident per SM stagger their prologues against each
// other's store streams (the hiding R3's 2-resident geometry lacked), and
// the single kernel node eliminates the ~4 us two-node graph launch gap.
// ---------------------------------------------------------------------------
__global__ __launch_bounds__(UP_THREADS) void synth_kernel(
        const float* __restrict__ amp_in,
        const float* __restrict__ freq_in,
        float4* __restrict__ out,
        float* __restrict__ freq_out) {
    __shared__ __align__(16) float s_x0[CH];
    __shared__ __align__(16) float s_x1[CH];
    __shared__ float sw[HOP];

    const int tid = threadIdx.x;
    const int seg = blockIdx.x;

    int segn = seg + 1;
    if (segn % FRAMES == 0) segn = seg;       // clamp: frame 250 == frame 249

    if (tid < 200) {
        // Controls for this block's two endpoint frames.
        const int which = tid / CH;            // 0 -> seg (x0), 1 -> segn (x1)
        const int c     = tid - which * CH;    // channel 0..99
        const int idx   = (which ? segn : seg) * CH + c;

        // Issue both loads immediately; math below overlaps their latency.
        const float a_raw = amp_in[idx];
        const float f_raw = freq_in[idx];

        const float LOG10_F  = 2.302585092994046f;   // ln(10)
        const float MIDI_MAX = 119.21309485364912f;  // 12*(log2 8k-log2 440)+69
        const float NYQ      = 22050.0f;             // SR / 2

        float uf   = 1.0f / (1.0f + expf(-f_raw));
        float freq = 440.0f * exp2f((uf * MIDI_MAX - 69.0f) * (1.0f / 12.0f));

        float sa  = 1.0f / (1.0f + expf(-a_raw));
        float amp = 2.0f * powf(sa, LOG10_F) + 1e-7f;

        float aa = ((freq * (float)(c + 1) < NYQ) ? 1.0f : 0.0f) + 1e-4f;
        float v  = amp * aa;

        if (which) {
            s_x1[c] = v;
        } else {
            s_x0[c] = v;
            freq_out[seg * CH + c] = freq;     // exactly once per segment
        }
    } else {
        // Window table: threads 200..399 cover 256 entries (56 do two).
        const int r = tid - 200;               // 0..199
        sw[r] = 0.5f - 0.5f * cospif((float)r * (1.0f / 256.0f));
        if (r < HOP - 200) {
            const int r2 = r + 200;            // 200..255
            sw[r2] = 0.5f - 0.5f * cospif((float)r2 * (1.0f / 256.0f));
        }
    }

    __syncthreads();

    // ---- R10 store engine (measured optimum: 16 stores / endpoint load) ----
    const int c4 = tid % 25;                  // channel float4-group (fixed)
    const int r0 = tid / 25;                  // base row (0..15)

    const float4 x0 = *reinterpret_cast<const float4*>(&s_x0[c4 * 4]);
    const float4 x1 = *reinterpret_cast<const float4*>(&s_x1[c4 * 4]);
    float4 d;
    d.x = x1.x - x0.x;
    d.y = x1.y - x0.y;
    d.z = x1.z - x0.z;
    d.w = x1.w - x0.w;

    float4* o = out + (size_t)seg * SEG_VEC4 + tid;

#pragma unroll
    for (int k = 0; k < STORES; k++) {
        const float w = sw[r0 + 16 * k];
        float4 v;
        v.x = fmaf(d.x, w, x0.x);
        v.y = fmaf(d.y, w, x0.y);
        v.z = fmaf(d.z, w, x0.z);
        v.w = fmaf(d.w, w, x0.w);
        o[UP_THREADS * k] = v;
    }
}

// ---------------------------------------------------------------------------
extern "C" void kernel_launch(void* const* d_in, const int* in_sizes, int n_in,
                              void* d_out, int out_size) {
    const float* amps  = (const float*)d_in[0];
    const float* freqs = (const float*)d_in[1];
    float* out = (float*)d_out;

    synth_kernel<<<SEGS, UP_THREADS>>>(amps, freqs, (float4*)out,
                                       out + ENV_ELEMS);
}

// round 15
// speedup vs baseline: 1.4049x; 1.0054x over previous
#include <cuda_runtime.h>
#include <math.h>

// Shapes
//   amplitudes, frequencies : [8, 250, 100] f32
//   out = concat( amp_env [8, 64000, 100], freq_env [8, 250, 100] )  f32
#define B            8
#define FRAMES       250
#define CH           100
#define CTRL_ELEMS   (B * FRAMES * CH)        // 200000
#define T_OUT        64000
#define HOP          256                      // 64000 / 250
#define ENV_ELEMS    (B * T_OUT * CH)         // 51200000
#define SEGS         (B * FRAMES)             // 2000 segments
#define SEG_VEC4     (HOP * (CH / 4))         // 6400 float4 per segment
#define UP_THREADS   400                      // 16 rows x 25 float4-groups
#define STORES       16                       // float4 stores per thread

// ---------------------------------------------------------------------------
// Single fused kernel: one block per segment (b, j), 400 threads.
//
// Prologue: threads 0..199 compute get_controls for (seg, c)/(segn, c) into
// s_x0/s_x1 (LDGs issued first; transcendental math overlaps their latency);
// the which=0 half writes this segment's 100 frequency outputs. One barrier.
// ~4 co-resident blocks per SM stagger prologues against store streams.
//
// Store phase: thread tid owns fixed channel float4-group c4 = tid % 25 and
// base row r0 = tid / 25 (0..15); endpoints read once, d = x1 - x0, then 16
// fully coalesced float4 stores (iteration k -> float4 index seg*6400 +
// 400k + tid, row 16k + r0). Window weights use the closed form
//   w_k = 0.5 - 0.5*cos(pi*(r0 + 16k)/256)
//       = 0.5 - HC[k]*c0 + HS[k]*s0,   (c0,s0) = cos/sin(pi*r0/256),
// with HC[k] = 0.5*cos(k*pi/16), HS[k] = 0.5*sin(k*pi/16) compile-time
// immediates: 2 independent FMAs per weight, NO shared memory reads in the
// loop (R11's serial-recurrence mistake avoided — every store independent).
// ---------------------------------------------------------------------------
__global__ __launch_bounds__(UP_THREADS) void synth_kernel(
        const float* __restrict__ amp_in,
        const float* __restrict__ freq_in,
        float4* __restrict__ out,
        float* __restrict__ freq_out) {
    __shared__ __align__(16) float s_x0[CH];
    __shared__ __align__(16) float s_x1[CH];

    const int tid = threadIdx.x;
    const int seg = blockIdx.x;

    int segn = seg + 1;
    if (segn % FRAMES == 0) segn = seg;       // clamp: frame 250 == frame 249

    if (tid < 200) {
        // Controls for this block's two endpoint frames.
        const int which = tid / CH;            // 0 -> seg (x0), 1 -> segn (x1)
        const int c     = tid - which * CH;    // channel 0..99
        const int idx   = (which ? segn : seg) * CH + c;

        // Issue both loads immediately; math below overlaps their latency.
        const float a_raw = amp_in[idx];
        const float f_raw = freq_in[idx];

        const float LOG10_F  = 2.302585092994046f;   // ln(10)
        const float MIDI_MAX = 119.21309485364912f;  // 12*(log2 8k-log2 440)+69
        const float NYQ      = 22050.0f;             // SR / 2

        float uf   = 1.0f / (1.0f + expf(-f_raw));
        float freq = 440.0f * exp2f((uf * MIDI_MAX - 69.0f) * (1.0f / 12.0f));

        float sa  = 1.0f / (1.0f + expf(-a_raw));
        float amp = 2.0f * powf(sa, LOG10_F) + 1e-7f;

        float aa = ((freq * (float)(c + 1) < NYQ) ? 1.0f : 0.0f) + 1e-4f;
        float v  = amp * aa;

        if (which) {
            s_x1[c] = v;
        } else {
            s_x0[c] = v;
            freq_out[seg * CH + c] = freq;     // exactly once per segment
        }
    }

    // Per-thread base angle for the window closed form (overlaps prologue).
    const int c4 = tid % 25;                  // channel float4-group (fixed)
    const int r0 = tid / 25;                  // base row (0..15)
    float c0, s0;
    sincospif((float)r0 * (1.0f / 256.0f), &s0, &c0);

    // HC[k] = 0.5*cos(k*pi/16), HS[k] = 0.5*sin(k*pi/16) — fold to immediates.
    const float HC[STORES] = {
         0.5000000000f,  0.4903926402f,  0.4619397663f,  0.4157348062f,
         0.3535533906f,  0.2777851165f,  0.1913417162f,  0.0975451610f,
         0.0000000000f, -0.0975451610f, -0.1913417162f, -0.2777851165f,
        -0.3535533906f, -0.4157348062f, -0.4619397663f, -0.4903926402f };
    const float HS[STORES] = {
         0.0000000000f,  0.0975451610f,  0.1913417162f,  0.2777851165f,
         0.3535533906f,  0.4157348062f,  0.4619397663f,  0.4903926402f,
         0.5000000000f,  0.4903926402f,  0.4619397663f,  0.4157348062f,
         0.3535533906f,  0.2777851165f,  0.1913417162f,  0.0975451610f };

    __syncthreads();

    const float4 x0 = *reinterpret_cast<const float4*>(&s_x0[c4 * 4]);
    const float4 x1 = *reinterpret_cast<const float4*>(&s_x1[c4 * 4]);
    float4 d;
    d.x = x1.x - x0.x;
    d.y = x1.y - x0.y;
    d.z = x1.z - x0.z;
    d.w = x1.w - x0.w;

    float4* o = out + (size_t)seg * SEG_VEC4 + tid;

#pragma unroll
    for (int k = 0; k < STORES; k++) {
        // w = 0.5 - HC[k]*c0 + HS[k]*s0  (independent per k; no LDS)
        const float w = fmaf(HS[k], s0, fmaf(-HC[k], c0, 0.5f));
        float4 v;
        v.x = fmaf(d.x, w, x0.x);
        v.y = fmaf(d.y, w, x0.y);
        v.z = fmaf(d.z, w, x0.z);
        v.w = fmaf(d.w, w, x0.w);
        o[UP_THREADS * k] = v;
    }
}

// ---------------------------------------------------------------------------
extern "C" void kernel_launch(void* const* d_in, const int* in_sizes, int n_in,
                              void* d_out, int out_size) {
    const float* amps  = (const float*)d_in[0];
    const float* freqs = (const float*)d_in[1];
    float* out = (float*)d_out;

    synth_kernel<<<SEGS, UP_THREADS>>>(amps, freqs, (float4*)out,
                                       out + ENV_ELEMS);
}

// round 16
// speedup vs baseline: 1.4062x; 1.0009x over previous
#include <cuda_runtime.h>
#include <math.h>

// Shapes
//   amplitudes, frequencies : [8, 250, 100] f32
//   out = concat( amp_env [8, 64000, 100], freq_env [8, 250, 100] )  f32
#define B            8
#define FRAMES       250
#define CH           100
#define CTRL_ELEMS   (B * FRAMES * CH)        // 200000
#define T_OUT        64000
#define HOP          256                      // 64000 / 250
#define ENV_ELEMS    (B * T_OUT * CH)         // 51200000
#define SEGS         (B * FRAMES)             // 2000 segments
#define SEG_VEC4     (HOP * (CH / 4))         // 6400 float4 per segment
#define UP_THREADS   400                      // 16 rows x 25 float4-groups
#define STORES       16                       // float4 stores per thread

// ---------------------------------------------------------------------------
// Single fused kernel: one block per segment (b, j), 400 threads.
//
// Prologue: threads 0..199 compute get_controls for (seg, c)/(segn, c) into
// s_x0/s_x1 (LDGs issued first; FAST-INTRINSIC transcendental chain —
// __expf/__logf — minimizes the serial latency before the store stream);
// the which=0 half writes this segment's 100 frequency outputs. One barrier.
// ~5 co-resident blocks per SM stagger prologues against store streams.
//
// Store phase: thread tid owns fixed channel float4-group c4 = tid % 25 and
// base row r0 = tid / 25 (0..15); endpoints read once, d = x1 - x0, then 16
// fully coalesced float4 stores (iteration k -> float4 index seg*6400 +
// 400k + tid, row 16k + r0). Window weights via the dependence-free closed
// form  w_k = 0.5 - HC[k]*c0 + HS[k]*s0,  (c0,s0) = cos/sin(pi*r0/256),
// HC[k] = 0.5*cos(k*pi/16), HS[k] = 0.5*sin(k*pi/16) immediates. No LDS in
// the loop; every store independent.
// ---------------------------------------------------------------------------
__global__ __launch_bounds__(UP_THREADS) void synth_kernel(
        const float* __restrict__ amp_in,
        const float* __restrict__ freq_in,
        float4* __restrict__ out,
        float* __restrict__ freq_out) {
    __shared__ __align__(16) float s_x0[CH];
    __shared__ __align__(16) float s_x1[CH];

    const int tid = threadIdx.x;
    const int seg = blockIdx.x;

    int segn = seg + 1;
    if (segn % FRAMES == 0) segn = seg;       // clamp: frame 250 == frame 249

    if (tid < 200) {
        // Controls for this block's two endpoint frames.
        const int which = tid / CH;            // 0 -> seg (x0), 1 -> segn (x1)
        const int c     = tid - which * CH;    // channel 0..99
        const int idx   = (which ? segn : seg) * CH + c;

        // Issue both loads immediately; math below overlaps their latency.
        const float a_raw = amp_in[idx];
        const float f_raw = freq_in[idx];

        const float LOG10_F  = 2.302585092994046f;   // ln(10)
        const float MIDI_MAX = 119.21309485364912f;  // 12*(log2 8k-log2 440)+69
        const float NYQ      = 22050.0f;             // SR / 2

        // sigmoid via fast exp (MUFU EX2): rel err ~2^-21 << 1e-3 gate
        float uf   = 1.0f / (1.0f + __expf(-f_raw));
        float freq = 440.0f * exp2f((uf * MIDI_MAX - 69.0f) * (1.0f / 12.0f));

        float sa  = 1.0f / (1.0f + __expf(-a_raw));
        // sa^ln(10) = exp(ln(10) * ln(sa)); underflow region is masked by the
        // +1e-7 floor, so fast log/exp precision is ample.
        float amp = 2.0f * __expf(LOG10_F * __logf(sa)) + 1e-7f;

        float aa = ((freq * (float)(c + 1) < NYQ) ? 1.0f : 0.0f) + 1e-4f;
        float v  = amp * aa;

        if (which) {
            s_x1[c] = v;
        } else {
            s_x0[c] = v;
            freq_out[seg * CH + c] = freq;     // exactly once per segment
        }
    }

    // Per-thread base angle for the window closed form (overlaps prologue).
    const int c4 = tid % 25;                  // channel float4-group (fixed)
    const int r0 = tid / 25;                  // base row (0..15)
    float c0, s0;
    sincospif((float)r0 * (1.0f / 256.0f), &s0, &c0);

    // HC[k] = 0.5*cos(k*pi/16), HS[k] = 0.5*sin(k*pi/16) — fold to immediates.
    const float HC[STORES] = {
         0.5000000000f,  0.4903926402f,  0.4619397663f,  0.4157348062f,
         0.3535533906f,  0.2777851165f,  0.1913417162f,  0.0975451610f,
         0.0000000000f, -0.0975451610f, -0.1913417162f, -0.2777851165f,
        -0.3535533906f, -0.4157348062f, -0.4619397663f, -0.4903926402f };
    const float HS[STORES] = {
         0.0000000000f,  0.0975451610f,  0.1913417162f,  0.2777851165f,
         0.3535533906f,  0.4157348062f,  0.4619397663f,  0.4903926402f,
         0.5000000000f,  0.4903926402f,  0.4619397663f,  0.4157348062f,
         0.3535533906f,  0.2777851165f,  0.1913417162f,  0.0975451610f };

    __syncthreads();

    const float4 x0 = *reinterpret_cast<const float4*>(&s_x0[c4 * 4]);
    const float4 x1 = *reinterpret_cast<const float4*>(&s_x1[c4 * 4]);
    float4 d;
    d.x = x1.x - x0.x;
    d.y = x1.y - x0.y;
    d.z = x1.z - x0.z;
    d.w = x1.w - x0.w;

    float4* o = out + (size_t)seg * SEG_VEC4 + tid;

#pragma unroll
    for (int k = 0; k < STORES; k++) {
        // w = 0.5 - HC[k]*c0 + HS[k]*s0  (independent per k; no LDS)
        const float w = fmaf(HS[k], s0, fmaf(-HC[k], c0, 0.5f));
        float4 v;
        v.x = fmaf(d.x, w, x0.x);
        v.y = fmaf(d.y, w, x0.y);
        v.z = fmaf(d.z, w, x0.z);
        v.w = fmaf(d.w, w, x0.w);
        o[UP_THREADS * k] = v;
    }
}

// ---------------------------------------------------------------------------
extern "C" void kernel_launch(void* const* d_in, const int* in_sizes, int n_in,
                              void* d_out, int out_size) {
    const float* amps  = (const float*)d_in[0];
    const float* freqs = (const float*)d_in[1];
    float* out = (float*)d_out;

    synth_kernel<<<SEGS, UP_THREADS>>>(amps, freqs, (float4*)out,
                                       out + ENV_ELEMS);
}